// round 3
// baseline (speedup 1.0000x reference)
#include <cuda_runtime.h>
#include <math.h>

// Problem shape (fixed by the benchmark):
// video [B=8, C=1024, T=64, W=14, H=14] fp32
// params mu_x, mu_y, sigma_x, sigma_y: [N=3] fp32
// out [B, C*N] = einsum('bctwh,nwh->bcn', video, filters) / T
#define N_FILT 3
#define W_DIM 14
#define H_DIM 14
#define WH 196              // W*H
#define WH4 49              // WH/4
#define T_DIM 64
#define T_GROUPS 5          // time-slices per CTA thread-group
#define ACTIVE_THREADS (WH4 * T_GROUPS)  // 245
#define SLAB (T_DIM * WH)   // 12544 floats per (b,c)
#define SLAB4 (SLAB / 4)    // 3136 float4 per (b,c)
#define GRID_CTAS 740       // 148 SMs * 5 resident CTAs

// ---------------------------------------------------------------------------
// Fused persistent kernel:
//  1) Each CTA computes the 3 normalized Gaussian filters (scaled by
//     1/(sum+eps)/T) into shared memory, once.
//  2) Each thread hoists its 12 filter values into registers.
//  3) Grid-stride loop over (b,c) slabs: inner loop = 1 LDG.128 + 12 FFMA.
// ---------------------------------------------------------------------------
__global__ __launch_bounds__(256, 5)
void fused_kernel(const float* __restrict__ video,
                  const float* __restrict__ mu_x,
                  const float* __restrict__ mu_y,
                  const float* __restrict__ sigma_x,
                  const float* __restrict__ sigma_y,
                  float* __restrict__ out,
                  int n_bc) {
    const int tid = threadIdx.x;
    const int wid = tid >> 5;
    const int lid = tid & 31;

    // [3][196] filter values; row stride 196 floats = 784 B (16B-aligned)
    __shared__ float fsm[N_FILT][WH];
    __shared__ float red[8][N_FILT];   // per-warp partials (reused later)

    // ---- Phase 1: compute filters --------------------------------------
    {
        float val[N_FILT];
        float wsum[N_FILT];
        #pragma unroll
        for (int n = 0; n < N_FILT; n++) {
            float mx = tanhf(mu_x[n]);
            float my = tanhf(mu_y[n]);
            float sgx = 1.0f / (1.0f + expf(-sigma_x[n]));
            float sgy = 1.0f / (1.0f + expf(-sigma_y[n]));
            float sx = expf(1.5f - 2.0f * sgx);
            float sy = expf(1.5f - 2.0f * sgy);
            float inv_x = 1.0f / (sx * sx + 1e-6f);
            float inv_y = 1.0f / (sy * sy + 1e-6f);
            float mux = (float)(W_DIM - 1) * ((mx + 1.0f) * 0.5f);
            float muy = (float)(H_DIM - 1) * ((my + 1.0f) * 0.5f);

            float v = 0.0f;
            if (tid < WH) {
                int w = tid / H_DIM;
                int h = tid - w * H_DIM;
                float dx = (float)w - mux;
                float dy = (float)h - muy;
                v = expf(-0.5f * (dx * dx * inv_x + dy * dy * inv_y));
            }
            val[n] = v;
            // warp-level sum
            float s = v;
            #pragma unroll
            for (int off = 16; off > 0; off >>= 1)
                s += __shfl_xor_sync(0xFFFFFFFFu, s, off);
            wsum[n] = s;
        }
        if (lid == 0) {
            red[wid][0] = wsum[0];
            red[wid][1] = wsum[1];
            red[wid][2] = wsum[2];
        }
        __syncthreads();
        if (tid < WH) {
            #pragma unroll
            for (int n = 0; n < N_FILT; n++) {
                float s = 0.0f;
                #pragma unroll
                for (int w = 0; w < 8; w++) s += red[w][n];
                float scale = 1.0f / ((s + 1e-6f) * (float)T_DIM);
                fsm[n][tid] = val[n] * scale;
            }
        }
        __syncthreads();
    }

    // ---- Phase 2: hoist this thread's filter float4s into registers ----
    float4 f0 = make_float4(0.f, 0.f, 0.f, 0.f);
    float4 f1 = f0, f2 = f0;
    int g = 0, p = 0;
    if (tid < ACTIVE_THREADS) {
        g = tid / WH4;          // time-group 0..4
        p = tid - g * WH4;      // spatial float4 position 0..48
        f0 = ((const float4*)fsm[0])[p];
        f1 = ((const float4*)fsm[1])[p];
        f2 = ((const float4*)fsm[2])[p];
    }
    __syncthreads();   // fsm no longer needed; red[] reused below

    // ---- Phase 3: persistent grid-stride over (b,c) slabs --------------
    for (int bc = blockIdx.x; bc < n_bc; bc += GRID_CTAS) {
        float a0 = 0.0f, a1 = 0.0f, a2 = 0.0f;

        if (tid < ACTIVE_THREADS) {
            const float4* vp = (const float4*)video + (size_t)bc * SLAB4 + p;
            #pragma unroll 4
            for (int t = g; t < T_DIM; t += T_GROUPS) {
                float4 v = __ldg(&vp[t * WH4]);
                a0 += v.x * f0.x + v.y * f0.y + v.z * f0.z + v.w * f0.w;
                a1 += v.x * f1.x + v.y * f1.y + v.z * f1.z + v.w * f1.w;
                a2 += v.x * f2.x + v.y * f2.y + v.z * f2.z + v.w * f2.w;
            }
        }

        #pragma unroll
        for (int off = 16; off > 0; off >>= 1) {
            a0 += __shfl_xor_sync(0xFFFFFFFFu, a0, off);
            a1 += __shfl_xor_sync(0xFFFFFFFFu, a1, off);
            a2 += __shfl_xor_sync(0xFFFFFFFFu, a2, off);
        }
        if (lid == 0) {
            red[wid][0] = a0;
            red[wid][1] = a1;
            red[wid][2] = a2;
        }
        __syncthreads();
        if (tid < N_FILT) {
            float s = 0.0f;
            #pragma unroll
            for (int w = 0; w < 8; w++) s += red[w][tid];
            out[(size_t)bc * N_FILT + tid] = s;
        }
        __syncthreads();   // protect red[] before next slab's writes
    }
}

// ---------------------------------------------------------------------------
extern "C" void kernel_launch(void* const* d_in, const int* in_sizes, int n_in,
                              void* d_out, int out_size) {
    const float* video   = (const float*)d_in[0];
    const float* mu_x    = (const float*)d_in[1];
    const float* mu_y    = (const float*)d_in[2];
    const float* sigma_x = (const float*)d_in[3];
    const float* sigma_y = (const float*)d_in[4];
    float* out = (float*)d_out;

    const int n_bc = in_sizes[0] / SLAB;  // B*C = 8192
    const int grid = (n_bc < GRID_CTAS) ? n_bc : GRID_CTAS;

    fused_kernel<<<grid, 256>>>(video, mu_x, mu_y, sigma_x, sigma_y, out, n_bc);
}